// round 11
// baseline (speedup 1.0000x reference)
#include <cuda_runtime.h>

// Fixed problem shape
#define BB 256
#define TT 4096
#define CC 16
#define HH 20
#define ZL 10
#define K  8
#define NC (TT / K)   // 512 chunks

typedef unsigned long long u64;

__device__ __forceinline__ u64 pack2(float a, float b) {
    u64 r; asm("mov.b64 %0,{%1,%2};" : "=l"(r) : "f"(a), "f"(b)); return r;
}
__device__ __forceinline__ void unpack2(u64 v, float& a, float& b) {
    asm("mov.b64 {%0,%1},%2;" : "=f"(a), "=f"(b) : "l"(v));
}
__device__ __forceinline__ void fma2(u64& d, u64 a, u64 b) {
    asm("fma.rn.f32x2 %0,%1,%2,%0;" : "+l"(d) : "l"(a), "l"(b));
}
__device__ __forceinline__ u64 add2(u64 a, u64 b) {
    u64 r; asm("add.rn.f32x2 %0,%1,%2;" : "=l"(r) : "l"(a), "l"(b)); return r;
}
__device__ __forceinline__ float tanha(float x) {
    float y; asm("tanh.approx.f32 %0,%1;" : "=f"(y) : "f"(x)); return y;
}

// ---------------------------------------------------------------------------
// "RN/Z all-lane" layout: the 60 gate values per step are spread over 30
// lanes as f32x2 pairs so each fma2 carries 60 useful MACs instead of 40:
//   lane i (0..19):   pair = (r-part_i , n-part_i)     [r prescaled by 0.5]
//   lane 20+m (m<10): pair = (z-part_2m, z-part_2m+1)  [z prescaled by 0.5]
// Multiplier operands are DUPLICATED pairs (v_j, v_j) (h rows stored as
// pack2(h,h); x rows stored duplicated by the DMA).
// Recurrence dot: 20 fma2 (was 30); no hsum tail. r,n co-located per lane;
// z crosses lanes via same-warp STS.64 -> LDS.32 (LSU is in-order per warp).
//
// Warp map (SMSP = w%4; chain warps at HIGH wid):
//   w0=GX0+xDMA+head(A) S0   w1=GX1(A) S1   w2=GX0+..(B) S2   w3=GX1(B) S3
//   w4=L0(A)            S0   w5=L1(A)  S1   w6=L0(B)     S2   w7=L1(B)  S3
// Lags: GX0 chunk c, L0 c-1, GX1 c-2, L1 c-3, head c-4. Rings 2-deep.
// sigmoid(s) = fma(tanh.approx(prescaled_sum), 0.5, 0.5).
// ---------------------------------------------------------------------------
__global__ void __launch_bounds__(256, 1)
fused_gru_kernel(const float* __restrict__ x,      // [B,T,C]
                 const float* __restrict__ h0in,   // [B,2,H]
                 const float* __restrict__ W_ih0, const float* __restrict__ W_hh0,
                 const float* __restrict__ b_ih0, const float* __restrict__ b_hh0,
                 const float* __restrict__ W_ih1, const float* __restrict__ W_hh1,
                 const float* __restrict__ b_ih1, const float* __restrict__ b_hh1,
                 const float* __restrict__ W_o,   const float* __restrict__ b_o,
                 float* __restrict__ out)          // o[B*T] then h_n[B,2,H]
{
    __shared__ __align__(16) u64   s_g0 [2][2][K][30];     // RN/Z gx0   7.5 KB
    __shared__ __align__(16) u64   s_g1 [2][2][K][30];     // RN/Z gx1   7.5 KB
    __shared__ __align__(16) u64   s_h0d[2][2][K][HH];     // dup h0     5 KB
    __shared__ __align__(16) u64   s_h1d[2][2][K][HH];     // dup h1     5 KB
    __shared__ __align__(16) float s_xd [2][2][K][2 * CC]; // dup x      4 KB
    __shared__ __align__(16) float s_z  [2][2][2 * ZL];    // z exchange 0.3 KB

    const int tid = threadIdx.x;
    const int w   = tid >> 5;
    const int i   = tid & 31;
    const unsigned FULL = 0xFFFFFFFFu;

    const bool rn = (i < HH);                 // (r,n) lanes
    const bool zl = (i >= HH) && (i < HH + ZL);
    const int  m  = i - HH;                   // z pair index

    const bool low  = (w < 4);
    const int bs    = low ? (w >> 1) : ((w - 4) >> 1);
    const int kind  = w & 1;   // low: 0=GX0+head 1=GX1 ; high: 0=L0 1=L1
    const int b     = blockIdx.x * 2 + bs;
    const float* xb = x + (size_t)b * TT * CC;

    // ---- prime x chunk 0 (GX0 warps): 128 floats = 32 float4, duplicated ---
    if (low && kind == 0) {
        float4 v = ((const float4*)xb)[i];
        float4* dst = (float4*)&s_xd[bs][0][0][0];
        dst[2 * i]     = make_float4(v.x, v.x, v.y, v.y);
        dst[2 * i + 1] = make_float4(v.z, v.z, v.w, v.w);
    }
    __syncthreads();

    if (low && kind == 0) {
        // ============ GX0 (RN/Z) + x DMA + output head =======================
        u64 wp[CC]; u64 bb = 0;
        float wof[HH];
        if (rn) {
#pragma unroll
            for (int c2 = 0; c2 < CC; ++c2)
                wp[c2] = pack2(0.5f * W_ih0[i * CC + c2],
                               W_ih0[(2 * HH + i) * CC + c2]);
            bb = pack2(0.5f * b_ih0[i], b_ih0[2 * HH + i]);
        } else if (zl) {
#pragma unroll
            for (int c2 = 0; c2 < CC; ++c2)
                wp[c2] = pack2(0.5f * W_ih0[(HH + 2 * m) * CC + c2],
                               0.5f * W_ih0[(HH + 2 * m + 1) * CC + c2]);
            bb = pack2(0.5f * b_ih0[HH + 2 * m], 0.5f * b_ih0[HH + 2 * m + 1]);
        } else {
#pragma unroll
            for (int c2 = 0; c2 < CC; ++c2) wp[c2] = 0ULL;
        }
#pragma unroll
        for (int j = 0; j < HH; ++j) wof[j] = W_o[j];
        const float bo = b_o[0];
        float* ob = out + (size_t)b * TT;

        for (int c = 0; c < NC + 4; ++c) {
            float4 pf;
            const bool dopf = (c + 1 < NC);
            if (dopf) pf = ((const float4*)(xb + (size_t)(c + 1) * K * CC))[i];

            if (c < NC) {
                const float* xs = &s_xd[bs][c & 1][0][0];
                u64* go = &s_g0[bs][c & 1][0][0];
#pragma unroll 2
                for (int s = 0; s < K; ++s) {
                    const ulonglong2* xv = (const ulonglong2*)(xs + s * 2 * CC);
                    u64 acc0 = bb, acc1 = 0ULL;
#pragma unroll
                    for (int k2 = 0; k2 < 8; ++k2) {
                        ulonglong2 p = xv[k2];          // ((xa,xa),(xb,xb))
                        fma2(acc0, wp[2 * k2],     p.x);
                        fma2(acc1, wp[2 * k2 + 1], p.y);
                    }
                    if (i < 30) go[s * 30 + i] = add2(acc0, acc1);
                }
            }
            // output head for chunk c-4: lane l<K handles step l
            const int ch = c - 4;
            if (ch >= 0 && i < K) {
                const float4* hv = (const float4*)&s_h1d[bs][ch & 1][i][0];
                float acc = bo;
#pragma unroll
                for (int k2 = 0; k2 < 10; ++k2) {
                    float4 q = hv[k2];                  // (h2k,h2k,h2k+1,h2k+1)
                    acc = fmaf(wof[2 * k2],     q.x, acc);
                    acc = fmaf(wof[2 * k2 + 1], q.z, acc);
                }
                ob[ch * K + i] = acc;
            }
            // deposit duplicated x chunk c+1
            if (dopf) {
                float4* dst = (float4*)&s_xd[bs][(c + 1) & 1][0][0];
                dst[2 * i]     = make_float4(pf.x, pf.x, pf.y, pf.y);
                dst[2 * i + 1] = make_float4(pf.z, pf.z, pf.w, pf.w);
            }
            __syncthreads();
        }
    } else if (low) {
        // ============ GX1 (RN/Z): gx1 = W_ih1 . h0 ===========================
        u64 wi[HH]; u64 bb = 0;
        if (rn) {
#pragma unroll
            for (int j = 0; j < HH; ++j)
                wi[j] = pack2(0.5f * W_ih1[i * HH + j],
                              W_ih1[(2 * HH + i) * HH + j]);
            bb = pack2(0.5f * b_ih1[i], b_ih1[2 * HH + i]);
        } else if (zl) {
#pragma unroll
            for (int j = 0; j < HH; ++j)
                wi[j] = pack2(0.5f * W_ih1[(HH + 2 * m) * HH + j],
                              0.5f * W_ih1[(HH + 2 * m + 1) * HH + j]);
            bb = pack2(0.5f * b_ih1[HH + 2 * m], 0.5f * b_ih1[HH + 2 * m + 1]);
        } else {
#pragma unroll
            for (int j = 0; j < HH; ++j) wi[j] = 0ULL;
        }

        for (int c = 0; c < NC + 4; ++c) {
            const int cg = c - 2;
            if (cg >= 0 && cg < NC) {
                const u64* hr = &s_h0d[bs][cg & 1][0][0];
                u64* go = &s_g1[bs][cg & 1][0][0];
#pragma unroll 2
                for (int s = 0; s < K; ++s) {
                    const ulonglong2* hv = (const ulonglong2*)(hr + s * HH);
                    u64 hq[HH];
#pragma unroll
                    for (int k2 = 0; k2 < 10; ++k2) {
                        ulonglong2 p = hv[k2];
                        hq[2 * k2] = p.x; hq[2 * k2 + 1] = p.y;
                    }
                    u64 acc0 = bb, acc1 = 0ULL;
#pragma unroll
                    for (int j = 0; j < HH; j += 2) {
                        fma2(acc0, wi[j],     hq[j]);
                        fma2(acc1, wi[j + 1], hq[j + 1]);
                    }
                    if (i < 30) go[s * 30 + i] = add2(acc0, acc1);
                }
            }
            __syncthreads();
        }
    } else {
        // ============ L0 / L1: recurrence chains (RN/Z layout) ===============
        const bool isL0  = (kind == 0);
        const float* Whh = isL0 ? W_hh0 : W_hh1;
        const float* bhh = isL0 ? b_hh0 : b_hh1;
        const int lag    = isL0 ? 1 : 3;
        const int layer  = kind;

        u64 wg[HH]; u64 bb = 0; float h = 0.f;
        if (rn) {
#pragma unroll
            for (int j = 0; j < HH; ++j)
                wg[j] = pack2(0.5f * Whh[i * HH + j],
                              Whh[(2 * HH + i) * HH + j]);
            bb = pack2(0.5f * bhh[i], bhh[2 * HH + i]);
            h = h0in[(b * 2 + layer) * HH + i];
        } else if (zl) {
#pragma unroll
            for (int j = 0; j < HH; ++j)
                wg[j] = pack2(0.5f * Whh[(HH + 2 * m) * HH + j],
                              0.5f * Whh[(HH + 2 * m + 1) * HH + j]);
            bb = pack2(0.5f * bhh[HH + 2 * m], 0.5f * bhh[HH + 2 * m + 1]);
        } else {
#pragma unroll
            for (int j = 0; j < HH; ++j) wg[j] = 0ULL;
        }

        // initial duplicated broadcast of h
        u64 hp[HH];
#pragma unroll
        for (int j = 0; j < HH; ++j) {
            float hj = __shfl_sync(FULL, h, j);
            hp[j] = pack2(hj, hj);
        }

        float* zx = &s_z[bs][kind][0];
        const int gi = (i < 30) ? i : 0;
        const int zi = rn ? i : 0;

        for (int c = 0; c < NC + 4; ++c) {
            const int cc = c - lag;
            if (cc >= 0 && cc < NC) {
                const u64* gin = isL0 ? &s_g0[bs][cc & 1][0][0]
                                      : &s_g1[bs][cc & 1][0][0];
                u64* hd = isL0 ? &s_h0d[bs][cc & 1][0][0]
                               : &s_h1d[bs][cc & 1][0][0];
#pragma unroll 2
                for (int s = 0; s < K; ++s) {
                    const u64 g = gin[s * 30 + gi];
                    float ga, gb_; unpack2(g, ga, gb_);
                    // rn lanes: fold gxr into acc; keep gxn (gb_) out (n gate
                    // multiplies only the recurrent part by r). z lanes: fold both.
                    u64 acc0 = bb;
                    u64 acc1 = rn ? pack2(ga, 0.f) : g;
#pragma unroll
                    for (int j = 0; j < HH; j += 2) {
                        fma2(acc0, wg[j],     hp[j]);
                        fma2(acc1, wg[j + 1], hp[j + 1]);
                    }
                    float sa, sb; unpack2(add2(acc0, acc1), sa, sb);
                    const float v1 = fmaf(tanha(sa), 0.5f, 0.5f); // r | z_2m
                    const float t2 = tanha(rn ? fmaf(v1, sb, gb_) : sb); // n | tanh(pre_z1)
                    // z lanes publish (z_2m, z_2m+1); same-warp in-order LSU
                    if (zl) *(u64*)(zx + 2 * m) = pack2(v1, fmaf(t2, 0.5f, 0.5f));
                    asm volatile("" ::: "memory");
                    const float z = zx[zi];
                    h = fmaf(z, h - t2, t2);          // rn lanes: n = t2
                    if (rn) hd[s * HH + i] = pack2(h, h);
                    asm volatile("" ::: "memory");
                    const ulonglong2* hv = (const ulonglong2*)(hd + s * HH);
#pragma unroll
                    for (int k2 = 0; k2 < 10; ++k2) {
                        ulonglong2 p = hv[k2];
                        hp[2 * k2] = p.x; hp[2 * k2 + 1] = p.y;
                    }
                }
            }
            __syncthreads();
        }
        if (rn) out[(size_t)BB * TT + (b * 2 + layer) * HH + i] = h;
    }
}

// ---------------------------------------------------------------------------
extern "C" void kernel_launch(void* const* d_in, const int* in_sizes, int n_in,
                              void* d_out, int out_size) {
    const float* x     = (const float*)d_in[0];
    const float* h0    = (const float*)d_in[1];
    const float* W_ih0 = (const float*)d_in[2];
    const float* W_hh0 = (const float*)d_in[3];
    const float* b_ih0 = (const float*)d_in[4];
    const float* b_hh0 = (const float*)d_in[5];
    const float* W_ih1 = (const float*)d_in[6];
    const float* W_hh1 = (const float*)d_in[7];
    const float* b_ih1 = (const float*)d_in[8];
    const float* b_hh1 = (const float*)d_in[9];
    const float* W_o   = (const float*)d_in[10];
    const float* b_o   = (const float*)d_in[11];

    fused_gru_kernel<<<BB / 2, 256>>>(x, h0, W_ih0, W_hh0, b_ih0, b_hh0,
                                      W_ih1, W_hh1, b_ih1, b_hh1, W_o, b_o,
                                      (float*)d_out);
}

// round 12
// speedup vs baseline: 1.0475x; 1.0475x over previous
#include <cuda_runtime.h>

// Fixed problem shape
#define BB 256
#define TT 4096
#define CC 16
#define HH 20
#define K  16
#define NC (TT / K)   // 256 chunks

typedef unsigned long long u64;

__device__ __forceinline__ u64 pack2(float a, float b) {
    u64 r; asm("mov.b64 %0,{%1,%2};" : "=l"(r) : "f"(a), "f"(b)); return r;
}
__device__ __forceinline__ void unpack2(u64 v, float& a, float& b) {
    asm("mov.b64 {%0,%1},%2;" : "=f"(a), "=f"(b) : "l"(v));
}
__device__ __forceinline__ void fma2(u64& d, u64 a, u64 b) {
    asm("fma.rn.f32x2 %0,%1,%2,%0;" : "+l"(d) : "l"(a), "l"(b));
}
__device__ __forceinline__ float hsum2(u64 v) {
    float x, y; unpack2(v, x, y); return x + y;
}
__device__ __forceinline__ float tanha(float x) {
    float y; asm("tanh.approx.f32 %0,%1;" : "=f"(y) : "f"(x)); return y;
}

// ---------------------------------------------------------------------------
// R9 pipeline + RN/Z-packed GX warps. 2 batches per block, 8 warps, 128 blocks.
// Warp map (SMSP = w%4; chain warps at HIGH wid):
//   w0=GX0+xDMA+head(A) S0   w1=GX1(A) S1   w2=GX0+..(B) S2   w3=GX1(B) S3
//   w4=L0(A)            S0   w5=L1(A)  S1   w6=L0(B)     S2   w7=L1(B)  S3
// Lags: GX0 chunk c, L0 c-1, GX1 c-2, L1 c-3, head c-4. Rings 2-deep.
//
// GX warps use the RN/Z all-lane layout (fma2 count 30->20 / 24->16):
//   lane i<20:    acc pair = (r-part_i [prescaled 0.5], n-part_i)
//   lane 20+m<30: acc pair = (z-part_2m, z-part_2m+1)  [prescaled 0.5]
// with DUPLICATED multiplier pairs (v_j,v_j) built via ALU MOVs (off fma pipe).
// Output format: s_grn[s][i] = (gr_i, gn_i) u64 ; s_gz[s][i] = gz_i scalar.
// Chain warps are IDENTICAL to round 9 (30 fma2, j-paired, self-contained)
// except they read gx as 1 LDS.64 + 1 LDS.32.
// sigmoid(s) = fma(tanh.approx(prescaled_sum), 0.5, 0.5).
// ---------------------------------------------------------------------------
__global__ void __launch_bounds__(256, 1)
fused_gru_kernel(const float* __restrict__ x,      // [B,T,C]
                 const float* __restrict__ h0in,   // [B,2,H]
                 const float* __restrict__ W_ih0, const float* __restrict__ W_hh0,
                 const float* __restrict__ b_ih0, const float* __restrict__ b_hh0,
                 const float* __restrict__ W_ih1, const float* __restrict__ W_hh1,
                 const float* __restrict__ b_ih1, const float* __restrict__ b_hh1,
                 const float* __restrict__ W_o,   const float* __restrict__ b_o,
                 float* __restrict__ out)          // o[B*T] then h_n[B,2,H]
{
    __shared__ __align__(16) u64   s_grn0[2][2][K][HH];  // (gr,gn) gx0  10 KB
    __shared__ __align__(16) float s_gz0 [2][2][K][HH];  // gz gx0        5 KB
    __shared__ __align__(16) u64   s_grn1[2][2][K][HH];  // (gr,gn) gx1  10 KB
    __shared__ __align__(16) float s_gz1 [2][2][K][HH];  //               5 KB
    __shared__ __align__(16) float s_h0  [2][2][K][HH];  // h0 rows       5 KB
    __shared__ __align__(16) float s_h1  [2][2][K][HH];  // h1 rows       5 KB
    __shared__ __align__(16) float s_x   [2][2][K][CC];  // x             4 KB

    const int tid = threadIdx.x;
    const int w   = tid >> 5;
    const int i   = tid & 31;
    const bool act = (i < HH);
    const unsigned FULL = 0xFFFFFFFFu;

    const bool rn = (i < HH);
    const bool zl = (i >= HH) && (i < 30);
    const int  m  = i - HH;                 // z pair index

    const bool low  = (w < 4);
    const int bs    = low ? (w >> 1) : ((w - 4) >> 1);
    const int kind  = w & 1;   // low: 0=GX0+head 1=GX1 ; high: 0=L0 1=L1
    const int b     = blockIdx.x * 2 + bs;
    const float* xb = x + (size_t)b * TT * CC;

    // ---- prime x chunk 0 (GX0 warps): 256 floats = 64 float4 ---------------
    if (low && kind == 0) {
        const float4* src = (const float4*)xb;
        float4* dst = (float4*)&s_x[bs][0][0][0];
        dst[i] = src[i]; dst[i + 32] = src[i + 32];
    }
    __syncthreads();

    if (low && kind == 0) {
        // ============ GX0 (RN/Z) + x DMA + output head =======================
        u64 wp[CC]; u64 bb = 0ULL;
        u64 wo2[10];
        if (rn) {
#pragma unroll
            for (int c2 = 0; c2 < CC; ++c2)
                wp[c2] = pack2(0.5f * W_ih0[i * CC + c2],
                               W_ih0[(2 * HH + i) * CC + c2]);
            bb = pack2(0.5f * b_ih0[i], b_ih0[2 * HH + i]);
        } else if (zl) {
#pragma unroll
            for (int c2 = 0; c2 < CC; ++c2)
                wp[c2] = pack2(0.5f * W_ih0[(HH + 2 * m) * CC + c2],
                               0.5f * W_ih0[(HH + 2 * m + 1) * CC + c2]);
            bb = pack2(0.5f * b_ih0[HH + 2 * m], 0.5f * b_ih0[HH + 2 * m + 1]);
        } else {
#pragma unroll
            for (int c2 = 0; c2 < CC; ++c2) wp[c2] = 0ULL;
        }
#pragma unroll
        for (int k = 0; k < 10; ++k)
            wo2[k] = pack2(W_o[2 * k], W_o[2 * k + 1]);
        const float bo = b_o[0];
        float* ob = out + (size_t)b * TT;

        for (int c = 0; c < NC + 4; ++c) {
            float4 pf0, pf1;
            const bool pf = (c + 1 < NC);
            if (pf) {
                const float4* src = (const float4*)(xb + (size_t)(c + 1) * K * CC);
                pf0 = src[i]; pf1 = src[i + 32];
            }
            if (c < NC) {
                const float* xs = &s_x[bs][c & 1][0][0];
                u64*   grn = &s_grn0[bs][c & 1][0][0];
                float* gz_ = &s_gz0 [bs][c & 1][0][0];
#pragma unroll 4
                for (int s = 0; s < K; ++s) {
                    const float4* xv4 = (const float4*)(xs + s * CC);
                    float4 xa = xv4[0], xb4 = xv4[1], xc = xv4[2], xd = xv4[3];
                    float xf[CC] = {xa.x, xa.y, xa.z, xa.w, xb4.x, xb4.y, xb4.z, xb4.w,
                                    xc.x, xc.y, xc.z, xc.w, xd.x, xd.y, xd.z, xd.w};
                    u64 acc = bb;
#pragma unroll
                    for (int c2 = 0; c2 < CC; ++c2)
                        fma2(acc, wp[c2], pack2(xf[c2], xf[c2]));
                    if (rn)      grn[s * HH + i] = acc;
                    else if (zl) *(u64*)(gz_ + s * HH + 2 * m) = acc;
                }
            }
            // output head for chunk c-4: lane l<K handles step l
            const int ch = c - 4;
            if (ch >= 0 && ch < NC && i < K) {
                const ulonglong2* hv2 = (const ulonglong2*)&s_h1[bs][ch & 1][i][0];
                ulonglong2 p0 = hv2[0], p1 = hv2[1], p2 = hv2[2], p3 = hv2[3], p4 = hv2[4];
                u64 hq[10] = {p0.x, p0.y, p1.x, p1.y, p2.x, p2.y, p3.x, p3.y, p4.x, p4.y};
                u64 acc = pack2(bo, 0.f);
#pragma unroll
                for (int k = 0; k < 10; ++k) fma2(acc, wo2[k], hq[k]);
                ob[ch * K + i] = hsum2(acc);
            }
            if (pf) {
                float4* dst = (float4*)&s_x[bs][(c + 1) & 1][0][0];
                dst[i] = pf0; dst[i + 32] = pf1;
            }
            __syncthreads();
        }
    } else if (low) {
        // ============ GX1 (RN/Z): gx1 = W_ih1 . h0 ===========================
        u64 wi[HH]; u64 bb = 0ULL;
        if (rn) {
#pragma unroll
            for (int j = 0; j < HH; ++j)
                wi[j] = pack2(0.5f * W_ih1[i * HH + j],
                              W_ih1[(2 * HH + i) * HH + j]);
            bb = pack2(0.5f * b_ih1[i], b_ih1[2 * HH + i]);
        } else if (zl) {
#pragma unroll
            for (int j = 0; j < HH; ++j)
                wi[j] = pack2(0.5f * W_ih1[(HH + 2 * m) * HH + j],
                              0.5f * W_ih1[(HH + 2 * m + 1) * HH + j]);
            bb = pack2(0.5f * b_ih1[HH + 2 * m], 0.5f * b_ih1[HH + 2 * m + 1]);
        } else {
#pragma unroll
            for (int j = 0; j < HH; ++j) wi[j] = 0ULL;
        }

        for (int c = 0; c < NC + 4; ++c) {
            const int cg = c - 2;
            if (cg >= 0 && cg < NC) {
                const float* hr = &s_h0[bs][cg & 1][0][0];
                u64*   grn = &s_grn1[bs][cg & 1][0][0];
                float* gz_ = &s_gz1 [bs][cg & 1][0][0];
#pragma unroll 4
                for (int s = 0; s < K; ++s) {
                    const float4* hv4 = (const float4*)(hr + s * HH);
                    float4 a = hv4[0], b4 = hv4[1], c4 = hv4[2], d = hv4[3], e = hv4[4];
                    float hf[HH] = {a.x, a.y, a.z, a.w, b4.x, b4.y, b4.z, b4.w,
                                    c4.x, c4.y, c4.z, c4.w, d.x, d.y, d.z, d.w,
                                    e.x, e.y, e.z, e.w};
                    u64 acc = bb;
#pragma unroll
                    for (int j = 0; j < HH; ++j)
                        fma2(acc, wi[j], pack2(hf[j], hf[j]));
                    if (rn)      grn[s * HH + i] = acc;
                    else if (zl) *(u64*)(gz_ + s * HH + 2 * m) = acc;
                }
            }
            __syncthreads();
        }
    } else {
        // ============ L0 / L1: recurrence chains (identical to round 9) ======
        const bool isL0  = (kind == 0);
        const float* Whh = isL0 ? W_hh0 : W_hh1;
        const float* bhh = isL0 ? b_hh0 : b_hh1;
        const int lag    = isL0 ? 1 : 3;
        const int layer  = kind;

        u64 wh[30];
        float br = 0.f, bz = 0.f, bn = 0.f, h = 0.f;
#pragma unroll
        for (int g = 0; g < 3; ++g) {
            const float sc = (g < 2) ? 0.5f : 1.0f;
#pragma unroll
            for (int k = 0; k < 10; ++k)
                wh[g * 10 + k] = act ? pack2(sc * Whh[(g * HH + i) * HH + 2 * k],
                                             sc * Whh[(g * HH + i) * HH + 2 * k + 1])
                                     : pack2(0.f, 0.f);
        }
        if (act) {
            br = 0.5f * bhh[i]; bz = 0.5f * bhh[HH + i]; bn = bhh[2 * HH + i];
            h = h0in[(b * 2 + layer) * HH + i];
        }

        // initial broadcast of h (once)
        u64 hp[10];
#pragma unroll
        for (int k = 0; k < 10; ++k)
            hp[k] = pack2(__shfl_sync(FULL, h, 2 * k),
                          __shfl_sync(FULL, h, 2 * k + 1));

        for (int c = 0; c < NC + 4; ++c) {
            const int cc = c - lag;
            if (cc >= 0 && cc < NC) {
                const u64*   grn = isL0 ? &s_grn0[bs][cc & 1][0][0]
                                        : &s_grn1[bs][cc & 1][0][0];
                const float* gzp = isL0 ? &s_gz0[bs][cc & 1][0][0]
                                        : &s_gz1[bs][cc & 1][0][0];
                float* hw = isL0 ? &s_h0[bs][cc & 1][0][0]
                                 : &s_h1[bs][cc & 1][0][0];
#pragma unroll 2
                for (int s = 0; s < K; ++s) {
                    float gr = 0.f, gz = 0.f, gn = 0.f;
                    if (act) {
                        unpack2(grn[s * HH + i], gr, gn);
                        gz = gzp[s * HH + i];
                    }
                    // gate dots, grouped so r completes earliest
                    u64 ar = pack2(br, 0.f);
#pragma unroll
                    for (int k = 0; k < 10; ++k) fma2(ar, wh[k], hp[k]);
                    u64 az = pack2(bz, 0.f);
#pragma unroll
                    for (int k = 0; k < 10; ++k) fma2(az, wh[10 + k], hp[k]);
                    u64 an = pack2(bn, 0.f);
#pragma unroll
                    for (int k = 0; k < 10; ++k) fma2(an, wh[20 + k], hp[k]);

                    const float r = fmaf(tanha(gr + hsum2(ar)), 0.5f, 0.5f);
                    const float z = fmaf(tanha(gz + hsum2(az)), 0.5f, 0.5f);
                    const float n = tanha(fmaf(r, hsum2(an), gn));
                    h = fmaf(z, h - n, n);

                    // exchange through the s_h row (also feeds GX1/head warps)
                    if (act) hw[s * HH + i] = h;
                    __syncwarp();
                    const ulonglong2* hv2 = (const ulonglong2*)(hw + s * HH);
                    ulonglong2 p0 = hv2[0], p1 = hv2[1], p2 = hv2[2], p3 = hv2[3], p4 = hv2[4];
                    hp[0] = p0.x; hp[1] = p0.y; hp[2] = p1.x; hp[3] = p1.y;
                    hp[4] = p2.x; hp[5] = p2.y; hp[6] = p3.x; hp[7] = p3.y;
                    hp[8] = p4.x; hp[9] = p4.y;
                }
            }
            __syncthreads();
        }
        if (act) out[(size_t)BB * TT + (b * 2 + layer) * HH + i] = h;
    }
}

// ---------------------------------------------------------------------------
extern "C" void kernel_launch(void* const* d_in, const int* in_sizes, int n_in,
                              void* d_out, int out_size) {
    const float* x     = (const float*)d_in[0];
    const float* h0    = (const float*)d_in[1];
    const float* W_ih0 = (const float*)d_in[2];
    const float* W_hh0 = (const float*)d_in[3];
    const float* b_ih0 = (const float*)d_in[4];
    const float* b_hh0 = (const float*)d_in[5];
    const float* W_ih1 = (const float*)d_in[6];
    const float* W_hh1 = (const float*)d_in[7];
    const float* b_ih1 = (const float*)d_in[8];
    const float* b_hh1 = (const float*)d_in[9];
    const float* W_o   = (const float*)d_in[10];
    const float* b_o   = (const float*)d_in[11];

    fused_gru_kernel<<<BB / 2, 256>>>(x, h0, W_ih0, W_hh0, b_ih0, b_hh0,
                                      W_ih1, W_hh1, b_ih1, b_hh1, W_o, b_o,
                                      (float*)d_out);
}

// round 13
// speedup vs baseline: 1.2218x; 1.1663x over previous
#include <cuda_runtime.h>

// Fixed problem shape
#define BB 256
#define TT 4096
#define CC 16
#define HH 20
#define GG 60
#define K  16
#define NC (TT / K)   // 256 chunks

typedef unsigned long long u64;

__device__ __forceinline__ u64 pack2(float a, float b) {
    u64 r; asm("mov.b64 %0,{%1,%2};" : "=l"(r) : "f"(a), "f"(b)); return r;
}
__device__ __forceinline__ void unpack2(u64 v, float& a, float& b) {
    asm("mov.b64 {%0,%1},%2;" : "=f"(a), "=f"(b) : "l"(v));
}
__device__ __forceinline__ void fma2(u64& d, u64 a, u64 b) {
    asm("fma.rn.f32x2 %0,%1,%2,%0;" : "+l"(d) : "l"(a), "l"(b));
}
__device__ __forceinline__ float hsum2(u64 v) {
    float x, y; unpack2(v, x, y); return x + y;
}
__device__ __forceinline__ float tanha(float x) {
    float y; asm("tanh.approx.f32 %0,%1;" : "=f"(y) : "f"(x)); return y;
}

// ---------------------------------------------------------------------------
// R9 pipeline; GX warps rewritten as scalar-FFMA RN/Z over 30 lanes.
// Key identity: FFMA (1 MAC, rt 2) and fma.rn.f32x2 (2 MACs, rt 4) have the
// SAME MAC throughput per lane -> spreading the 60 gate dots over 30 lanes
// with plain scalar FFMA cuts GX pipe cycles by a third with ZERO packing
// overhead (no dup operands, no MOVs, no cross-lane traffic).
//   lane i<20:    computes rows (r_i [w prescaled 0.5], n_i)
//   lane 20+m<30: computes rows (z_2m, z_2m+1) [prescaled 0.5]
// Output layout per step: [60] floats (r 0..19 | z 20..39 | n 40..59) — the
// slot index IS the row index, so one uniform code path covers all lanes.
//
// Warp map (SMSP = w%4; chain warps at HIGH wid):
//   w0=GX0+xDMA+head(A) S0   w1=GX1(A) S1   w2=GX0+..(B) S2   w3=GX1(B) S3
//   w4=L0(A)            S0   w5=L1(A)  S1   w6=L0(B)     S2   w7=L1(B)  S3
// Lags: GX0 chunk c, L0 c-1, GX1 c-2, L1 c-3, head c-4. Rings 2-deep.
// Chain warps are bit-for-bit round 9 (30 fma2, j-paired, syncwarp exchange);
// only the gx read addresses changed (3 scalar LDS).
// sigmoid(s) = fma(tanh.approx(prescaled_sum), 0.5, 0.5).
// ---------------------------------------------------------------------------
__global__ void __launch_bounds__(256, 1)
fused_gru_kernel(const float* __restrict__ x,      // [B,T,C]
                 const float* __restrict__ h0in,   // [B,2,H]
                 const float* __restrict__ W_ih0, const float* __restrict__ W_hh0,
                 const float* __restrict__ b_ih0, const float* __restrict__ b_hh0,
                 const float* __restrict__ W_ih1, const float* __restrict__ W_hh1,
                 const float* __restrict__ b_ih1, const float* __restrict__ b_hh1,
                 const float* __restrict__ W_o,   const float* __restrict__ b_o,
                 float* __restrict__ out)          // o[B*T] then h_n[B,2,H]
{
    __shared__ __align__(16) float s_gx0[2][2][K][GG];  // 15 KB
    __shared__ __align__(16) float s_gx1[2][2][K][GG];  // 15 KB
    __shared__ __align__(16) float s_h0 [2][2][K][HH];  // 5 KB
    __shared__ __align__(16) float s_h1 [2][2][K][HH];  // 5 KB
    __shared__ __align__(16) float s_x  [2][2][K][CC];  // 4 KB

    const int tid = threadIdx.x;
    const int w   = tid >> 5;
    const int i   = tid & 31;
    const bool act = (i < HH);
    const unsigned FULL = 0xFFFFFFFFu;

    const bool low  = (w < 4);
    const int bs    = low ? (w >> 1) : ((w - 4) >> 1);
    const int kind  = w & 1;   // low: 0=GX0+head 1=GX1 ; high: 0=L0 1=L1
    const int b     = blockIdx.x * 2 + bs;
    const float* xb = x + (size_t)b * TT * CC;

    // RN/Z lane -> (rowA, rowB, scales). Slot index == row index.
    const bool gxon = (i < 30);
    int rowA = 0, rowB = 0; float scA = 0.f, scB = 0.f;
    if (i < HH)      { rowA = i;               scA = 0.5f; rowB = 2 * HH + i;      scB = 1.0f; }
    else if (gxon)   { rowA = HH + 2 * (i - HH); scA = 0.5f; rowB = rowA + 1;      scB = 0.5f; }

    // ---- prime x chunk 0 (GX0 warps): 256 floats = 64 float4 ---------------
    if (low && kind == 0) {
        const float4* src = (const float4*)xb;
        float4* dst = (float4*)&s_x[bs][0][0][0];
        dst[i] = src[i]; dst[i + 32] = src[i + 32];
    }
    __syncthreads();

    if (low && kind == 0) {
        // ============ GX0 (scalar RN/Z) + x DMA + output head ================
        float wA[CC], wB[CC], bA = 0.f, bB = 0.f;
        u64 wo2[10];
#pragma unroll
        for (int c2 = 0; c2 < CC; ++c2) {
            wA[c2] = scA * W_ih0[rowA * CC + c2];
            wB[c2] = scB * W_ih0[rowB * CC + c2];
        }
        bA = scA * b_ih0[rowA]; bB = scB * b_ih0[rowB];
#pragma unroll
        for (int k = 0; k < 10; ++k)
            wo2[k] = pack2(W_o[2 * k], W_o[2 * k + 1]);
        const float bo = b_o[0];
        float* ob = out + (size_t)b * TT;

        for (int c = 0; c < NC + 4; ++c) {
            float4 pf0, pf1;
            const bool pf = (c + 1 < NC);
            if (pf) {
                const float4* src = (const float4*)(xb + (size_t)(c + 1) * K * CC);
                pf0 = src[i]; pf1 = src[i + 32];
            }
            if (c < NC) {
                const float* xs = &s_x[bs][c & 1][0][0];
                float* go = &s_gx0[bs][c & 1][0][0];
#pragma unroll 4
                for (int s = 0; s < K; ++s) {
                    const float4* x4 = (const float4*)(xs + s * CC);
                    float4 p0 = x4[0], p1 = x4[1], p2 = x4[2], p3 = x4[3];
                    float xf[CC] = {p0.x, p0.y, p0.z, p0.w, p1.x, p1.y, p1.z, p1.w,
                                    p2.x, p2.y, p2.z, p2.w, p3.x, p3.y, p3.z, p3.w};
                    float A0 = bA, A1 = 0.f, B0 = bB, B1 = 0.f;
#pragma unroll
                    for (int j = 0; j < CC; j += 2) {
                        A0 = fmaf(wA[j],     xf[j],     A0);
                        A1 = fmaf(wA[j + 1], xf[j + 1], A1);
                        B0 = fmaf(wB[j],     xf[j],     B0);
                        B1 = fmaf(wB[j + 1], xf[j + 1], B1);
                    }
                    if (gxon) {
                        go[s * GG + rowA] = A0 + A1;
                        go[s * GG + rowB] = B0 + B1;
                    }
                }
            }
            // output head for chunk c-4: lane l<K handles step l
            const int ch = c - 4;
            if (ch >= 0 && ch < NC && i < K) {
                const ulonglong2* hv2 = (const ulonglong2*)&s_h1[bs][ch & 1][i][0];
                ulonglong2 p0 = hv2[0], p1 = hv2[1], p2 = hv2[2], p3 = hv2[3], p4 = hv2[4];
                u64 hq[10] = {p0.x, p0.y, p1.x, p1.y, p2.x, p2.y, p3.x, p3.y, p4.x, p4.y};
                u64 acc = pack2(bo, 0.f);
#pragma unroll
                for (int k = 0; k < 10; ++k) fma2(acc, wo2[k], hq[k]);
                ob[ch * K + i] = hsum2(acc);
            }
            if (pf) {
                float4* dst = (float4*)&s_x[bs][(c + 1) & 1][0][0];
                dst[i] = pf0; dst[i + 32] = pf1;
            }
            __syncthreads();
        }
    } else if (low) {
        // ============ GX1 (scalar RN/Z): gx1 = W_ih1 . h0 ====================
        float wA[HH], wB[HH], bA = 0.f, bB = 0.f;
#pragma unroll
        for (int j = 0; j < HH; ++j) {
            wA[j] = scA * W_ih1[rowA * HH + j];
            wB[j] = scB * W_ih1[rowB * HH + j];
        }
        bA = scA * b_ih1[rowA]; bB = scB * b_ih1[rowB];

        for (int c = 0; c < NC + 4; ++c) {
            const int cg = c - 2;
            if (cg >= 0 && cg < NC) {
                const float* hr = &s_h0[bs][cg & 1][0][0];
                float* go = &s_gx1[bs][cg & 1][0][0];
#pragma unroll 4
                for (int s = 0; s < K; ++s) {
                    const float4* h4 = (const float4*)(hr + s * HH);
                    float4 p0 = h4[0], p1 = h4[1], p2 = h4[2], p3 = h4[3], p4 = h4[4];
                    float hf[HH] = {p0.x, p0.y, p0.z, p0.w, p1.x, p1.y, p1.z, p1.w,
                                    p2.x, p2.y, p2.z, p2.w, p3.x, p3.y, p3.z, p3.w,
                                    p4.x, p4.y, p4.z, p4.w};
                    float A0 = bA, A1 = 0.f, B0 = bB, B1 = 0.f;
#pragma unroll
                    for (int j = 0; j < HH; j += 2) {
                        A0 = fmaf(wA[j],     hf[j],     A0);
                        A1 = fmaf(wA[j + 1], hf[j + 1], A1);
                        B0 = fmaf(wB[j],     hf[j],     B0);
                        B1 = fmaf(wB[j + 1], hf[j + 1], B1);
                    }
                    if (gxon) {
                        go[s * GG + rowA] = A0 + A1;
                        go[s * GG + rowB] = B0 + B1;
                    }
                }
            }
            __syncthreads();
        }
    } else {
        // ============ L0 / L1: recurrence chains (bit-for-bit round 9) =======
        const bool isL0  = (kind == 0);
        const float* Whh = isL0 ? W_hh0 : W_hh1;
        const float* bhh = isL0 ? b_hh0 : b_hh1;
        const int lag    = isL0 ? 1 : 3;
        const int layer  = kind;

        u64 wh[30];
        float br = 0.f, bz = 0.f, bn = 0.f, h = 0.f;
#pragma unroll
        for (int g = 0; g < 3; ++g) {
            const float sc = (g < 2) ? 0.5f : 1.0f;
#pragma unroll
            for (int k = 0; k < 10; ++k)
                wh[g * 10 + k] = act ? pack2(sc * Whh[(g * HH + i) * HH + 2 * k],
                                             sc * Whh[(g * HH + i) * HH + 2 * k + 1])
                                     : pack2(0.f, 0.f);
        }
        if (act) {
            br = 0.5f * bhh[i]; bz = 0.5f * bhh[HH + i]; bn = bhh[2 * HH + i];
            h = h0in[(b * 2 + layer) * HH + i];
        }

        // initial broadcast of h (once)
        u64 hp[10];
#pragma unroll
        for (int k = 0; k < 10; ++k)
            hp[k] = pack2(__shfl_sync(FULL, h, 2 * k),
                          __shfl_sync(FULL, h, 2 * k + 1));

        for (int c = 0; c < NC + 4; ++c) {
            const int cc = c - lag;
            if (cc >= 0 && cc < NC) {
                const float* gxp = isL0 ? &s_gx0[bs][cc & 1][0][0]
                                        : &s_gx1[bs][cc & 1][0][0];
                float* hw = isL0 ? &s_h0[bs][cc & 1][0][0]
                                 : &s_h1[bs][cc & 1][0][0];
#pragma unroll 2
                for (int s = 0; s < K; ++s) {
                    float gr = 0.f, gz = 0.f, gn = 0.f;
                    if (act) {
                        gr = gxp[s * GG + i];
                        gz = gxp[s * GG + HH + i];
                        gn = gxp[s * GG + 2 * HH + i];
                    }
                    // gate dots, grouped so r completes earliest
                    u64 ar = pack2(br, 0.f);
#pragma unroll
                    for (int k = 0; k < 10; ++k) fma2(ar, wh[k], hp[k]);
                    u64 az = pack2(bz, 0.f);
#pragma unroll
                    for (int k = 0; k < 10; ++k) fma2(az, wh[10 + k], hp[k]);
                    u64 an = pack2(bn, 0.f);
#pragma unroll
                    for (int k = 0; k < 10; ++k) fma2(an, wh[20 + k], hp[k]);

                    const float r = fmaf(tanha(gr + hsum2(ar)), 0.5f, 0.5f);
                    const float z = fmaf(tanha(gz + hsum2(az)), 0.5f, 0.5f);
                    const float n = tanha(fmaf(r, hsum2(an), gn));
                    h = fmaf(z, h - n, n);

                    // exchange through the s_h row (also feeds GX1/head warps)
                    if (act) hw[s * HH + i] = h;
                    __syncwarp();
                    const ulonglong2* hv2 = (const ulonglong2*)(hw + s * HH);
                    ulonglong2 p0 = hv2[0], p1 = hv2[1], p2 = hv2[2], p3 = hv2[3], p4 = hv2[4];
                    hp[0] = p0.x; hp[1] = p0.y; hp[2] = p1.x; hp[3] = p1.y;
                    hp[4] = p2.x; hp[5] = p2.y; hp[6] = p3.x; hp[7] = p3.y;
                    hp[8] = p4.x; hp[9] = p4.y;
                }
            }
            __syncthreads();
        }
        if (act) out[(size_t)BB * TT + (b * 2 + layer) * HH + i] = h;
    }
}

// ---------------------------------------------------------------------------
extern "C" void kernel_launch(void* const* d_in, const int* in_sizes, int n_in,
                              void* d_out, int out_size) {
    const float* x     = (const float*)d_in[0];
    const float* h0    = (const float*)d_in[1];
    const float* W_ih0 = (const float*)d_in[2];
    const float* W_hh0 = (const float*)d_in[3];
    const float* b_ih0 = (const float*)d_in[4];
    const float* b_hh0 = (const float*)d_in[5];
    const float* W_ih1 = (const float*)d_in[6];
    const float* W_hh1 = (const float*)d_in[7];
    const float* b_ih1 = (const float*)d_in[8];
    const float* b_hh1 = (const float*)d_in[9];
    const float* W_o   = (const float*)d_in[10];
    const float* b_o   = (const float*)d_in[11];

    fused_gru_kernel<<<BB / 2, 256>>>(x, h0, W_ih0, W_hh0, b_ih0, b_hh0,
                                      W_ih1, W_hh1, b_ih1, b_hh1, W_o, b_o,
                                      (float*)d_out);
}